// round 9
// baseline (speedup 1.0000x reference)
#include <cuda_runtime.h>
#include <cuda_bf16.h>
#include <math_constants.h>

// CircularBasisLayer: out[t, s*16+r] = rbf(D[id3[t]])[r] * gaussian_cbf(cos_phi[t])[s]
// E = 400000, T = 2000000, R = 16, S = 8. id3 is int32.
//
// Kernel 1: precompute rbf[E,16] (25.6 MB, L2-resident), __sincosf + Chebyshev.
// Kernel 2: one warp per 8 triplets (4KB contiguous output), 256-bit loads and
//           stores (sm_100+ v8.b32): 4 STG.256 + 4 LDG.256 per lane per batch.
//           Lane map (iter j): half=lane>>4, q=lane&15 -> triplet 2j+half,
//           s=q>>1, r-chunk=(q&1)*8.

#define NUM_RADIAL 16
#define NUM_SPHERICAL 8
#define MAX_EDGES 400000
#define WPT 8   // triplets per warp

__device__ float g_rbf[(size_t)MAX_EDGES * NUM_RADIAL];

__global__ __launch_bounds__(128)
void rbf_precompute_kernel(const float* __restrict__ D, int E) {
    int e = blockIdx.x * blockDim.x + threadIdx.x;
    if (e >= E) return;
    float d = D[e];
    float ds = d * (1.0f / 6.0f);
    float ds2 = ds * ds;
    float ds5 = ds2 * ds2 * ds;
    float env = 1.0f + ds5 * (-21.0f + ds * (35.0f - 15.0f * ds));
    if (ds >= 1.0f) env = 0.0f;
    const float norm = 0.09622504486493764f;  // sqrt(2 / 6^3)
    float pref = env * norm / d;
    float x = CUDART_PI_F * ds;   // x in [0, pi)

    // sin(n*x) via Chebyshev recurrence: s_{n+1} = 2 cos(x) * s_n - s_{n-1}
    float s1, c1;
    __sincosf(x, &s1, &c1);
    float twoc = 2.0f * c1;

    float buf[NUM_RADIAL];
    float sm1 = 0.0f;
    float s0 = s1;
    buf[0] = pref * s0;
#pragma unroll
    for (int r = 1; r < NUM_RADIAL; r++) {
        float sn = twoc * s0 - sm1;
        sm1 = s0;
        s0 = sn;
        buf[r] = pref * sn;
    }
    float* outp = g_rbf + (size_t)e * NUM_RADIAL;
#pragma unroll
    for (int q = 0; q < NUM_RADIAL / 4; q++) {
        reinterpret_cast<float4*>(outp)[q] =
            make_float4(buf[4 * q + 0], buf[4 * q + 1], buf[4 * q + 2], buf[4 * q + 3]);
    }
}

__device__ __forceinline__ void ldg_nc_v8(const float* p, float v[8]) {
    unsigned u0, u1, u2, u3, u4, u5, u6, u7;
    asm volatile("ld.global.nc.v8.b32 {%0,%1,%2,%3,%4,%5,%6,%7}, [%8];"
                 : "=r"(u0), "=r"(u1), "=r"(u2), "=r"(u3),
                   "=r"(u4), "=r"(u5), "=r"(u6), "=r"(u7)
                 : "l"(p));
    v[0] = __uint_as_float(u0); v[1] = __uint_as_float(u1);
    v[2] = __uint_as_float(u2); v[3] = __uint_as_float(u3);
    v[4] = __uint_as_float(u4); v[5] = __uint_as_float(u5);
    v[6] = __uint_as_float(u6); v[7] = __uint_as_float(u7);
}

__device__ __forceinline__ void stg_cs_v8(float* p, const float v[8]) {
    asm volatile("st.global.cs.v8.b32 [%0], {%1,%2,%3,%4,%5,%6,%7,%8};"
                 :: "l"(p),
                    "r"(__float_as_uint(v[0])), "r"(__float_as_uint(v[1])),
                    "r"(__float_as_uint(v[2])), "r"(__float_as_uint(v[3])),
                    "r"(__float_as_uint(v[4])), "r"(__float_as_uint(v[5])),
                    "r"(__float_as_uint(v[6])), "r"(__float_as_uint(v[7]))
                 : "memory");
}

__device__ __forceinline__ void store_cs4(float4* p, float4 v) {
    asm volatile("st.global.cs.v4.f32 [%0], {%1,%2,%3,%4};"
                 :: "l"(p), "f"(v.x), "f"(v.y), "f"(v.z), "f"(v.w) : "memory");
}

__global__ __launch_bounds__(128)
void triplet_outer_kernel(const float* __restrict__ cos_phi,
                          const int* __restrict__ id3,
                          float* __restrict__ out, int T) {
    size_t warpId = (blockIdx.x * (size_t)blockDim.x + threadIdx.x) >> 5;
    int lane = threadIdx.x & 31;
    size_t t0 = warpId * WPT;
    if (t0 >= (size_t)T) return;

    int half = lane >> 4;        // which of the 2 triplets this lane covers per iter
    int q = lane & 15;
    int s = q >> 1;
    int rh = q & 1;              // which 32B half of the rbf row
    float offset = -1.0f + (float)s * (2.0f / 7.0f);

    if (t0 + WPT <= (size_t)T) {
        // lane-uniform vector loads: broadcast within warp
        int4 e0 = __ldg(reinterpret_cast<const int4*>(id3 + t0));
        int4 e1 = __ldg(reinterpret_cast<const int4*>(id3 + t0 + 4));
        float4 c0 = __ldg(reinterpret_cast<const float4*>(cos_phi + t0));
        float4 c1 = __ldg(reinterpret_cast<const float4*>(cos_phi + t0 + 4));
        int   e[WPT] = {e0.x, e0.y, e0.z, e0.w, e1.x, e1.y, e1.z, e1.w};
        float c[WPT] = {c0.x, c0.y, c0.z, c0.w, c1.x, c1.y, c1.z, c1.w};

        // 4 independent 256-bit gathers in flight (L2-resident table)
        float r[4][8];
#pragma unroll
        for (int j = 0; j < 4; j++) {
            int tj = 2 * j + half;
            ldg_nc_v8(g_rbf + (size_t)e[tj] * NUM_RADIAL + rh * 8, r[j]);
        }

        float cb[4];
#pragma unroll
        for (int j = 0; j < 4; j++) {
            float df = c[2 * j + half] - offset;
            cb[j] = __expf(-6.125f * df * df);
        }

        // 4 KB contiguous output for the batch; 4 STG.256 per lane
        float* base = out + t0 * (NUM_RADIAL * NUM_SPHERICAL);
#pragma unroll
        for (int j = 0; j < 4; j++) {
            float o[8];
#pragma unroll
            for (int k = 0; k < 8; k++) o[k] = r[j][k] * cb[j];
            stg_cs_v8(base + j * 256 + lane * 8, o);
        }
    } else {
        // tail (T divisible by 8 in practice; kept for safety)
        int ss = lane >> 2;
        float offs = -1.0f + (float)ss * (2.0f / 7.0f);
        int rq = lane & 3;
        for (size_t t = t0; t < (size_t)T; t++) {
            int ee = id3[t];
            float cc = cos_phi[t];
            float df = cc - offs;
            float cbt = __expf(-6.125f * df * df);
            float4 r4 = __ldg(reinterpret_cast<const float4*>(
                                  g_rbf + (size_t)ee * NUM_RADIAL) + rq);
            float4 o = make_float4(r4.x * cbt, r4.y * cbt, r4.z * cbt, r4.w * cbt);
            store_cs4(reinterpret_cast<float4*>(
                          out + t * (NUM_RADIAL * NUM_SPHERICAL)) + lane, o);
        }
    }
}

extern "C" void kernel_launch(void* const* d_in, const int* in_sizes, int n_in,
                              void* d_out, int out_size) {
    const float* D_ca    = (const float*)d_in[0];
    const float* cos_phi = (const float*)d_in[1];
    const int* id3_ca    = (const int*)d_in[2];
    float* out = (float*)d_out;

    int E = in_sizes[0];
    int T = in_sizes[1];

    {
        int threads = 128;
        int blocks = (E + threads - 1) / threads;
        rbf_precompute_kernel<<<blocks, threads>>>(D_ca, E);
    }
    {
        int threads = 128;  // 4 warps/block, 8 triplets/warp
        long long numWarps = ((long long)T + WPT - 1) / WPT;
        int blocks = (int)((numWarps * 32 + threads - 1) / threads);
        triplet_outer_kernel<<<blocks, threads>>>(cos_phi, id3_ca, out, T);
    }
}

// round 10
// speedup vs baseline: 1.3427x; 1.3427x over previous
#include <cuda_runtime.h>
#include <cuda_bf16.h>
#include <math_constants.h>

// CircularBasisLayer: out[t, s*16+r] = rbf(D[id3[t]])[r] * gaussian_cbf(cos_phi[t])[s]
// E = 400000, T = 2000000, R = 16, S = 8. id3 is int32.
//
// FINAL (rounds 2-9): output write stream (1.024 GB) is the binding roofline;
// DRAM pinned at ~81% across all schedule shapes; v8 256-bit ops regress.
//   Kernel 1: precompute rbf[E,16] (25.6 MB, L2-resident), __sincosf + Chebyshev.
//   Kernel 2: one warp per 8 triplets, one-shot CTAs, 128-thread blocks,
//             8 independent LDG.128 gathers + 8 coalesced STG.128 .cs stores.

#define NUM_RADIAL 16
#define NUM_SPHERICAL 8
#define MAX_EDGES 400000
#define WPT 8   // triplets per warp

__device__ float g_rbf[(size_t)MAX_EDGES * NUM_RADIAL];

__global__ __launch_bounds__(128)
void rbf_precompute_kernel(const float* __restrict__ D, int E) {
    int e = blockIdx.x * blockDim.x + threadIdx.x;
    if (e >= E) return;
    float d = D[e];
    float ds = d * (1.0f / 6.0f);
    float ds2 = ds * ds;
    float ds5 = ds2 * ds2 * ds;
    float env = 1.0f + ds5 * (-21.0f + ds * (35.0f - 15.0f * ds));
    if (ds >= 1.0f) env = 0.0f;
    const float norm = 0.09622504486493764f;  // sqrt(2 / 6^3)
    float pref = env * norm / d;
    float x = CUDART_PI_F * ds;   // x in [0, pi) -- safe range for __sincosf

    // sin(n*x) via Chebyshev recurrence: s_{n+1} = 2 cos(x) * s_n - s_{n-1}
    float s1, c1;
    __sincosf(x, &s1, &c1);
    float twoc = 2.0f * c1;

    float buf[NUM_RADIAL];
    float sm1 = 0.0f;
    float s0 = s1;
    buf[0] = pref * s0;
#pragma unroll
    for (int r = 1; r < NUM_RADIAL; r++) {
        float sn = twoc * s0 - sm1;
        sm1 = s0;
        s0 = sn;
        buf[r] = pref * sn;
    }
    float* outp = g_rbf + (size_t)e * NUM_RADIAL;
#pragma unroll
    for (int q = 0; q < NUM_RADIAL / 4; q++) {
        reinterpret_cast<float4*>(outp)[q] =
            make_float4(buf[4 * q + 0], buf[4 * q + 1], buf[4 * q + 2], buf[4 * q + 3]);
    }
}

__device__ __forceinline__ void store_cs(float4* p, float4 v) {
    asm volatile("st.global.cs.v4.f32 [%0], {%1,%2,%3,%4};"
                 :: "l"(p), "f"(v.x), "f"(v.y), "f"(v.z), "f"(v.w) : "memory");
}

__global__ __launch_bounds__(128)
void triplet_outer_kernel(const float* __restrict__ cos_phi,
                          const int* __restrict__ id3,
                          float* __restrict__ out, int T) {
    size_t warpId = (blockIdx.x * (size_t)blockDim.x + threadIdx.x) >> 5;
    int lane = threadIdx.x & 31;
    size_t t0 = warpId * WPT;
    if (t0 >= (size_t)T) return;

    int s = lane >> 2;
    float offset = -1.0f + (float)s * (2.0f / 7.0f);   // linspace(-1,1,8)
    int rq = lane & 3;

    if (t0 + WPT <= (size_t)T) {
        // lane-uniform vector loads: broadcast within warp
        int4 e0 = __ldg(reinterpret_cast<const int4*>(id3 + t0));
        int4 e1 = __ldg(reinterpret_cast<const int4*>(id3 + t0 + 4));
        float4 c0 = __ldg(reinterpret_cast<const float4*>(cos_phi + t0));
        float4 c1 = __ldg(reinterpret_cast<const float4*>(cos_phi + t0 + 4));
        int   e[WPT] = {e0.x, e0.y, e0.z, e0.w, e1.x, e1.y, e1.z, e1.w};
        float c[WPT] = {c0.x, c0.y, c0.z, c0.w, c1.x, c1.y, c1.z, c1.w};

        // 8 independent gathers in flight (L2-resident table)
        float4 r[WPT];
#pragma unroll
        for (int j = 0; j < WPT; j++)
            r[j] = __ldg(reinterpret_cast<const float4*>(
                             g_rbf + (size_t)e[j] * NUM_RADIAL) + rq);

        float cb[WPT];
#pragma unroll
        for (int j = 0; j < WPT; j++) {
            float df = c[j] - offset;
            cb[j] = __expf(-6.125f * df * df);
        }

#pragma unroll
        for (int j = 0; j < WPT; j++) {
            float4 o = make_float4(r[j].x * cb[j], r[j].y * cb[j],
                                   r[j].z * cb[j], r[j].w * cb[j]);
            store_cs(reinterpret_cast<float4*>(
                         out + (t0 + j) * (NUM_RADIAL * NUM_SPHERICAL)) + lane, o);
        }
    } else {
        // tail (T divisible by 8 in practice; kept for safety)
        for (size_t t = t0; t < (size_t)T; t++) {
            int ee = id3[t];
            float cc = cos_phi[t];
            float df = cc - offset;
            float cb = __expf(-6.125f * df * df);
            float4 r4 = __ldg(reinterpret_cast<const float4*>(
                                  g_rbf + (size_t)ee * NUM_RADIAL) + rq);
            float4 o = make_float4(r4.x * cb, r4.y * cb, r4.z * cb, r4.w * cb);
            store_cs(reinterpret_cast<float4*>(
                         out + t * (NUM_RADIAL * NUM_SPHERICAL)) + lane, o);
        }
    }
}

extern "C" void kernel_launch(void* const* d_in, const int* in_sizes, int n_in,
                              void* d_out, int out_size) {
    const float* D_ca    = (const float*)d_in[0];
    const float* cos_phi = (const float*)d_in[1];
    const int* id3_ca    = (const int*)d_in[2];
    float* out = (float*)d_out;

    int E = in_sizes[0];
    int T = in_sizes[1];

    {
        int threads = 128;
        int blocks = (E + threads - 1) / threads;
        rbf_precompute_kernel<<<blocks, threads>>>(D_ca, E);
    }
    {
        int threads = 128;  // 4 warps/block, 8 triplets/warp -> 32 triplets/block
        long long numWarps = ((long long)T + WPT - 1) / WPT;
        int blocks = (int)((numWarps * 32 + threads - 1) / threads);
        triplet_outer_kernel<<<blocks, threads>>>(cos_phi, id3_ca, out, T);
    }
}